// round 6
// baseline (speedup 1.0000x reference)
#include <cuda_runtime.h>
#include <math.h>

#define NN 50000
#define EE 500000
#define GG 50
#define NPG 1000
#define NB  444          // 148 SMs x 3 blocks: all-resident (GB300 has 152 SMs, more slack)
#define NT  256
#define GTH (NB*NT)

// ---------------- scratch ----------------
__device__ __align__(16) float g_hr  [NN*64];   // raw (pre-pairnorm) node features
__device__ __align__(16) float g_a   [NN*64];
__device__ __align__(16) float g_b   [NN*64];
__device__ __align__(16) float g_aggr[NN*64];
__device__ int   g_cnt[NN];
__device__ int   g_rowptr[NN+1];
__device__ __align__(8) int2 g_csr[EE];         // {src, float_as_int(dist)}
__device__ __align__(16) float g_stats2[2][65]; // per-layer colsum[64]+sumsq
__device__ int   g_bsum[256];
__device__ int   g_barcnt = 0;
__device__ int   g_bargen = 0;

// ---- software grid barrier (all NB blocks resident by construction) ----
__device__ __forceinline__ void grid_barrier() {
    __syncthreads();
    if (threadIdx.x == 0) {
        __threadfence();
        int gen = *(volatile int*)&g_bargen;
        if (atomicAdd(&g_barcnt, 1) == (int)gridDim.x - 1) {
            atomicExch(&g_barcnt, 0);
            __threadfence();
            atomicAdd(&g_bargen, 1);
        } else {
            while (*(volatile int*)&g_bargen == gen) { }
        }
        __threadfence();
    }
    __syncthreads();
}

// ---------------- THE kernel ----------------
__global__ void __launch_bounds__(NT, 3) k_all(
    const float* __restrict__ hin,  const float* __restrict__ pos,
    const int*   __restrict__ ei,
    const float* __restrict__ Wemb, const float* __restrict__ bemb,
    const float* __restrict__ msgW, const float* __restrict__ msgb,
    const float* __restrict__ updW, const float* __restrict__ updb,
    const float* __restrict__ W1,   const float* __restrict__ b1,
    const float* __restrict__ W2,   const float* __restrict__ b2,
    float* __restrict__ out)
{
    __shared__ __align__(16) char smem_raw[(32*129 + 32*128 + 80) * 4];
    float* sXT   = (float*)smem_raw;            // [32][129]
    float* sW    = sXT + 32*129;                // up to [32][128]
    float* snorm = sW + 32*128;                 // [65]
    int*   sI    = (int*)smem_raw;              // scan overlay

    int tid = threadIdx.x;
    int bid = blockIdx.x;
    int gt  = bid * NT + tid;
    int lane = tid & 31;

    // ===== Ph0: init =====
    if (gt < 65) { g_stats2[0][gt] = 0.f; g_stats2[1][gt] = 0.f; }
    for (int i = gt; i < NN; i += GTH) g_cnt[i] = 0;
    grid_barrier();

    // ===== Ph1: count in-degree =====
    for (int e = gt; e < EE; e += GTH)
        atomicAdd(&g_cnt[ei[EE + e]], 1);
    grid_barrier();

    // ===== Ph2: per-block scan (blocks 0..195 cover NN) =====
    if (bid < 196) {
        int i = bid*256 + tid;
        int c = (i < NN) ? g_cnt[i] : 0;
        sI[tid] = c;
        __syncthreads();
        #pragma unroll
        for (int off = 1; off < 256; off <<= 1) {
            int t = 0;
            if (tid >= off) t = sI[tid - off];
            __syncthreads();
            sI[tid] += t;
            __syncthreads();
        }
        if (i < NN) g_rowptr[i] = sI[tid] - c;
        if (tid == 255) g_bsum[bid] = sI[255];
    }
    grid_barrier();

    // ===== Ph3: block 0 scans block sums =====
    if (bid == 0) {
        int c = (tid < 196) ? g_bsum[tid] : 0;
        sI[tid] = c;
        __syncthreads();
        #pragma unroll
        for (int off = 1; off < 256; off <<= 1) {
            int t = 0;
            if (tid >= off) t = sI[tid - off];
            __syncthreads();
            sI[tid] += t;
            __syncthreads();
        }
        if (tid < 196) g_bsum[tid] = sI[tid] - c;
    }
    grid_barrier();

    // ===== Ph4: globalize rowptr + fill cursors =====
    if (bid < 196) {
        int i = bid*256 + tid;
        if (i < NN) {
            int r = g_rowptr[i] + g_bsum[bid];
            g_rowptr[i] = r;
            g_cnt[i] = r;
        }
    }
    if (gt == 0) g_rowptr[NN] = EE;
    grid_barrier();

    // ===== Ph5: fill CSR + embedding =====
    for (int e = gt; e < EE; e += GTH) {
        int sn = ei[e];
        int d  = ei[EE + e];
        int p  = atomicAdd(&g_cnt[d], 1);
        float dx = pos[2*d]   - pos[2*sn];
        float dy = pos[2*d+1] - pos[2*sn+1];
        g_csr[p] = make_int2(sn, __float_as_int(sqrtf(dx*dx + dy*dy)));
    }
    {
        int c0 = lane * 2;
        for (int w = gt >> 5; w < NN; w += GTH >> 5) {
            float v0 = hin[w*5+0], v1 = hin[w*5+1], v2 = hin[w*5+2],
                  v3 = hin[w*5+3], v4 = hin[w*5+4];
            #pragma unroll
            for (int j = 0; j < 2; j++) {
                int c = c0 + j;
                float acc = bemb[c] + v0*Wemb[c] + v1*Wemb[64+c] + v2*Wemb[128+c]
                                    + v3*Wemb[192+c] + v4*Wemb[256+c];
                g_hr[w*64+c] = fmaxf(acc, 0.f);
            }
        }
    }
    grid_barrier();

    // ===== layer loop =====
    for (int l = 0; l < 2; l++) {
        const float* Wm = msgW + l*129*64;
        const float* bm = msgb + l*64;
        const float* Wu = updW + l*128*64;
        const float* bu = updb + l*64;

        // --- per-block pairnorm constants into snorm (identity for l=0) ---
        if (l == 0) {
            if (tid < 64) snorm[tid] = 0.f;
            if (tid == 0) snorm[64] = 1.f;
        } else {
            const float* st = g_stats2[l-1];
            if (tid < 64) snorm[tid] = st[tid] * (1.0f/NN);
            __syncthreads();
            if (tid == 0) {
                float ms = 0.f;
                #pragma unroll
                for (int j = 0; j < 64; j++) ms += snorm[j]*snorm[j];
                snorm[64] = 1.0f / sqrtf(1e-5f + st[64]*(1.0f/NN) - ms);
            }
        }
        __syncthreads();

        // --- Ph6: ab-GEMM, two 64-col halves (acc[8][4], regs ~79) ---
        if (bid < 391) {
            int base = bid * 128;
            float inv = snorm[64];
            int ng = tid & 15;
            int cg = tid >> 4;          // cols cg*4 .. +3 of 64
            #pragma unroll
            for (int half = 0; half < 2; half++) {
                float acc[8][4];
                #pragma unroll
                for (int i = 0; i < 8; i++)
                    #pragma unroll
                    for (int j = 0; j < 4; j++) acc[i][j] = 0.f;
                int rbase = half ? 64 : 0;
                for (int kc = 0; kc < 64; kc += 32) {
                    __syncthreads();
                    #pragma unroll
                    for (int it = 0; it < 4; it++) {
                        int idx = tid + 256*it;
                        int nl  = idx >> 3;
                        int kq  = idx & 7;
                        int n   = base + nl;
                        float4 v = make_float4(0.f,0.f,0.f,0.f);
                        if (n < NN) v = *(const float4*)&g_hr[n*64 + kc + kq*4];
                        float4 mu = *(const float4*)&snorm[kc + kq*4];
                        v.x = (v.x - mu.x)*inv; v.y = (v.y - mu.y)*inv;
                        v.z = (v.z - mu.z)*inv; v.w = (v.w - mu.w)*inv;
                        sXT[(kq*4+0)*129 + nl] = v.x;
                        sXT[(kq*4+1)*129 + nl] = v.y;
                        sXT[(kq*4+2)*129 + nl] = v.z;
                        sXT[(kq*4+3)*129 + nl] = v.w;
                    }
                    #pragma unroll
                    for (int it = 0; it < 8; it++) {
                        int idx = tid + 256*it;    // 2048 floats: [32 kk][64 c]
                        int c   = idx & 63;
                        int kk  = idx >> 6;
                        sW[kk*64 + c] = Wm[(rbase + kc + kk)*64 + c];
                    }
                    __syncthreads();
                    #pragma unroll
                    for (int kk = 0; kk < 32; kk++) {
                        float xv[8];
                        #pragma unroll
                        for (int i = 0; i < 8; i++) xv[i] = sXT[kk*129 + ng + 16*i];
                        float4 w = *(const float4*)&sW[kk*64 + cg*4];
                        float wv[4] = {w.x, w.y, w.z, w.w};
                        #pragma unroll
                        for (int i = 0; i < 8; i++)
                            #pragma unroll
                            for (int j = 0; j < 4; j++)
                                acc[i][j] = fmaf(xv[i], wv[j], acc[i][j]);
                    }
                }
                float* Out = half ? g_b : g_a;
                #pragma unroll
                for (int i = 0; i < 8; i++) {
                    int n = base + ng + 16*i;
                    if (n < NN)
                        *(float4*)&Out[n*64 + cg*4] =
                            make_float4(acc[i][0],acc[i][1],acc[i][2],acc[i][3]);
                }
            }
        }
        grid_barrier();

        // --- Ph7: gather (grid-stride warps, MLP=8) ---
        {
            int c0 = lane*2;
            float wdx = Wm[128*64 + c0], wdy = Wm[128*64 + c0 + 1];
            float bmx = bm[c0], bmy = bm[c0+1];
            for (int gw = gt >> 5; gw < NN; gw += GTH >> 5) {
                float2 av = *(const float2*)&g_a[gw*64 + c0];
                float pax = av.x + bmx;
                float pay = av.y + bmy;
                float ax = 0.f, ay = 0.f;
                int st = g_rowptr[gw], en = g_rowptr[gw+1];
                for (int eb = st; eb < en; eb += 8) {
                    int mm = en - eb; if (mm > 8) mm = 8;
                    int2 ed = make_int2(0, 0);
                    if (lane < mm) ed = g_csr[eb + lane];
                    float2 bv[8];
                    float  dv[8];
                    #pragma unroll
                    for (int j = 0; j < 8; j++) {
                        int sidx = __shfl_sync(0xffffffffu, ed.x, j);
                        int dbit = __shfl_sync(0xffffffffu, ed.y, j);
                        dv[j] = __int_as_float(dbit);
                        if (j < mm) bv[j] = *(const float2*)&g_b[sidx*64 + c0];
                    }
                    #pragma unroll
                    for (int j = 0; j < 8; j++) {
                        if (j < mm) {
                            ax += fmaxf(pax + bv[j].x + dv[j]*wdx, 0.f);
                            ay += fmaxf(pay + bv[j].y + dv[j]*wdy, 0.f);
                        }
                    }
                }
                *(float2*)&g_aggr[gw*64 + c0] = make_float2(ax, ay);
            }
        }
        grid_barrier();

        // --- Ph8: update GEMM (R1 tiling) + stats ---
        if (bid < 391) {
            int base = bid * 128;
            float inv = snorm[64];
            int ng = tid & 15;
            int cg = tid >> 4;          // cols cg*4..+3
            float acc[8][4];
            #pragma unroll
            for (int i = 0; i < 8; i++)
                #pragma unroll
                for (int j = 0; j < 4; j++) acc[i][j] = 0.f;

            for (int kc = 0; kc < 128; kc += 32) {
                __syncthreads();
                const bool fromH = (kc < 64);
                const float* Xsrc = fromH ? g_hr : g_aggr;
                int koff = kc & 63;
                #pragma unroll
                for (int it = 0; it < 4; it++) {
                    int idx = tid + 256*it;
                    int nl  = idx >> 3;
                    int kq  = idx & 7;
                    int n   = base + nl;
                    float4 v = make_float4(0.f,0.f,0.f,0.f);
                    if (n < NN) v = *(const float4*)&Xsrc[n*64 + koff + kq*4];
                    if (fromH) {
                        float4 mu = *(const float4*)&snorm[koff + kq*4];
                        v.x = (v.x - mu.x)*inv; v.y = (v.y - mu.y)*inv;
                        v.z = (v.z - mu.z)*inv; v.w = (v.w - mu.w)*inv;
                    }
                    sXT[(kq*4+0)*129 + nl] = v.x;
                    sXT[(kq*4+1)*129 + nl] = v.y;
                    sXT[(kq*4+2)*129 + nl] = v.z;
                    sXT[(kq*4+3)*129 + nl] = v.w;
                }
                #pragma unroll
                for (int it = 0; it < 8; it++) {
                    int idx = tid + 256*it;
                    int c   = idx & 63;
                    int kk  = idx >> 6;
                    sW[kk*68 + c] = Wu[(kc + kk)*64 + c];
                }
                __syncthreads();
                #pragma unroll
                for (int kk = 0; kk < 32; kk++) {
                    float xv[8];
                    #pragma unroll
                    for (int i = 0; i < 8; i++) xv[i] = sXT[kk*129 + ng + 16*i];
                    float4 w = *(const float4*)&sW[kk*68 + cg*4];
                    float wv[4] = {w.x, w.y, w.z, w.w};
                    #pragma unroll
                    for (int i = 0; i < 8; i++)
                        #pragma unroll
                        for (int j = 0; j < 4; j++)
                            acc[i][j] = fmaf(xv[i], wv[j], acc[i][j]);
                }
            }
            int c0 = cg*4;
            float4 bb = *(const float4*)&bu[c0];
            float bvv[4] = {bb.x, bb.y, bb.z, bb.w};
            float ls[4] = {0.f,0.f,0.f,0.f};
            float lss = 0.f;
            #pragma unroll
            for (int i = 0; i < 8; i++) {
                int n = base + ng + 16*i;
                if (n < NN) {
                    float o[4];
                    #pragma unroll
                    for (int j = 0; j < 4; j++) {
                        o[j] = fmaxf(acc[i][j] + bvv[j], 0.f);
                        ls[j] += o[j];
                        lss   += o[j]*o[j];
                    }
                    *(float4*)&g_hr[n*64 + c0] = make_float4(o[0],o[1],o[2],o[3]);
                }
            }
            #pragma unroll
            for (int off = 8; off >= 1; off >>= 1) {
                #pragma unroll
                for (int j = 0; j < 4; j++)
                    ls[j] += __shfl_down_sync(0xffffffffu, ls[j], off, 16);
                lss += __shfl_down_sync(0xffffffffu, lss, off, 16);
            }
            if ((tid & 15) == 0) {
                float* st = g_stats2[l];
                #pragma unroll
                for (int j = 0; j < 4; j++) atomicAdd(&st[c0 + j], ls[j]);
                atomicAdd(&st[64], lss);
            }
        }
        grid_barrier();
    }

    // ===== Ph9: pool + MLP (blocks 0..49) =====
    if (bid < GG) {
        // recompute final norm from layer-1 stats
        const float* st = g_stats2[1];
        if (tid < 64) snorm[tid] = st[tid] * (1.0f/NN);
        __syncthreads();
        if (tid == 0) {
            float ms = 0.f;
            #pragma unroll
            for (int j = 0; j < 64; j++) ms += snorm[j]*snorm[j];
            snorm[64] = 1.0f / sqrtf(1e-5f + st[64]*(1.0f/NN) - ms);
        }
        __syncthreads();

        float* red = sXT;          // [4][64] overlay
        float* hg  = red + 256;
        float* z   = hg + 64;
        int c     = tid & 63;
        int chunk = tid >> 6;
        float m = -3.4e38f;
        int nbeg = bid*NPG + chunk*(NPG/4);
        for (int i = 0; i < NPG/4; i++)
            m = fmaxf(m, g_hr[(nbeg + i)*64 + c]);
        red[chunk*64 + c] = m;
        __syncthreads();
        if (tid < 64) {
            float mr = fmaxf(fmaxf(red[tid], red[64+tid]),
                             fmaxf(red[128+tid], red[192+tid]));
            hg[tid] = (mr - snorm[tid]) * snorm[64];   // pairnorm monotone per column
        }
        __syncthreads();
        if (tid < 64) {
            float acc = b1[tid];
            for (int k = 0; k < 64; k++) acc = fmaf(hg[k], W1[k*64 + tid], acc);
            z[tid] = fmaxf(acc, 0.f);
        }
        __syncthreads();
        if (tid < 2) {
            float acc = b2[tid];
            for (int k = 0; k < 64; k++) acc = fmaf(z[k], W2[k*2 + tid], acc);
            out[bid*2 + tid] = acc;
        }
    }
}

// ---------------- launch ----------------
extern "C" void kernel_launch(void* const* d_in, const int* in_sizes, int n_in,
                              void* d_out, int out_size) {
    const float* h_in = (const float*)d_in[0];
    const float* pos  = (const float*)d_in[1];
    const int*   ei   = (const int*)  d_in[2];
    // d_in[3] = batch — contiguous 1000-node graphs, unused
    const float* Wemb = (const float*)d_in[4];
    const float* bemb = (const float*)d_in[5];
    const float* msgW = (const float*)d_in[6];
    const float* msgb = (const float*)d_in[7];
    const float* updW = (const float*)d_in[8];
    const float* updb = (const float*)d_in[9];
    const float* W1   = (const float*)d_in[10];
    const float* b1   = (const float*)d_in[11];
    const float* W2   = (const float*)d_in[12];
    const float* b2   = (const float*)d_in[13];
    float* out = (float*)d_out;

    k_all<<<NB, NT>>>(h_in, pos, ei, Wemb, bemb, msgW, msgb,
                      updW, updb, W1, b1, W2, b2, out);
}